// round 13
// baseline (speedup 1.0000x reference)
#include <cuda_runtime.h>
#include <cuda_bf16.h>
#include <math.h>
#include <stdint.h>

// ---------------- problem constants ----------------
#define BATCH  2
#define SEQ    2048
#define EMB    1024
#define NHEAD  16
#define HDIM   64
#define M_TOT  (BATCH * SEQ)       // 4096
#define C3     (3 * EMB)           // 3072
#define KDIM   1024
#define KW     (KDIM / 2)          // 512 packed words per row

// ---------------- scratch ----------------
__device__ float    g_qkv[M_TOT * C3];        // 48 MB (fp32 QKV)
__device__ uint32_t g_xhi[M_TOT * KW];        // x planes
__device__ uint32_t g_xlo[M_TOT * KW];
__device__ uint32_t g_wqthi[C3 * KW];         // Wqkv^T planes [N][K/2]
__device__ uint32_t g_wqtlo[C3 * KW];
__device__ uint32_t g_wpthi[EMB * KW];        // Wproj^T planes
__device__ uint32_t g_wptlo[EMB * KW];
__device__ uint32_t g_athi[M_TOT * KW];       // attention out planes
__device__ uint32_t g_atlo[M_TOT * KW];
__device__ uint32_t g_qhi[M_TOT * EMB / 2];   // Q*(0.125*log2e)
__device__ uint32_t g_qlo[M_TOT * EMB / 2];
__device__ uint32_t g_khi[M_TOT * EMB / 2];
__device__ uint32_t g_klo[M_TOT * EMB / 2];
__device__ uint32_t g_vthi[M_TOT * EMB / 2];  // V^T per head: [b][h][d][seq]
__device__ uint32_t g_vtlo[M_TOT * EMB / 2];

// ================= helpers =================
__device__ __forceinline__ uint32_t smem_u32(const void* p) {
    uint32_t a;
    asm("{ .reg .u64 t; cvta.to.shared.u64 t, %1; cvt.u32.u64 %0, t; }" : "=r"(a) : "l"(p));
    return a;
}
__device__ __forceinline__ void cpa16(uint32_t saddr, const void* g) {
    asm volatile("cp.async.cg.shared.global [%0], [%1], 16;" :: "r"(saddr), "l"(g));
}
#define CP_COMMIT()  asm volatile("cp.async.commit_group;")
#define CP_WAIT(n)   asm volatile("cp.async.wait_group %0;" :: "n"(n))

__device__ __forceinline__ void mma_bf16(float* d, uint32_t a0, uint32_t a1,
                                         uint32_t a2, uint32_t a3,
                                         uint32_t b0, uint32_t b1) {
    asm volatile(
        "mma.sync.aligned.m16n8k16.row.col.f32.bf16.bf16.f32 "
        "{%0,%1,%2,%3}, {%4,%5,%6,%7}, {%8,%9}, {%0,%1,%2,%3};"
        : "+f"(d[0]), "+f"(d[1]), "+f"(d[2]), "+f"(d[3])
        : "r"(a0), "r"(a1), "r"(a2), "r"(a3), "r"(b0), "r"(b1));
}
__device__ __forceinline__ void ldsm_x4(uint32_t& r0, uint32_t& r1, uint32_t& r2,
                                        uint32_t& r3, uint32_t addr) {
    asm volatile("ldmatrix.sync.aligned.m8n8.x4.shared.b16 {%0,%1,%2,%3}, [%4];"
                 : "=r"(r0), "=r"(r1), "=r"(r2), "=r"(r3) : "r"(addr));
}
__device__ __forceinline__ uint32_t pack_bf16x2(float e, float o) {
    uint32_t r;
    asm("cvt.rn.bf16x2.f32 %0, %1, %2;" : "=r"(r) : "f"(o), "f"(e));
    return r;
}
__device__ __forceinline__ void split2(float e, float o, uint32_t& whi, uint32_t& wlo) {
    whi = pack_bf16x2(e, o);
    float he = __uint_as_float(whi << 16);
    float ho = __uint_as_float(whi & 0xFFFF0000u);
    wlo = pack_bf16x2(e - he, o - ho);
}

// ================= bf16x3 mma.sync GEMM =================
// C[M,N] = A @ B + bias with A,B given as bf16 hi/lo planes:
//   A planes  [M][K/2 words] (row-major K)
//   Bt planes [N][K/2 words] (W^T, row-major K)
// CTA 128x128, BK=32, 8 warps (2Mx4N), warp 64x32, double buffer.
#define GROWB 144                                  // smem row bytes: hi 64 | lo 64 | pad 16
#define GSTAGE_BYTES (256 * GROWB)                 // 36864 (A rows 0..127, B rows 128..255)
#define GEMM_SMEM_BYTES (2 * GSTAGE_BYTES)         // 73728
#define GNIT (KDIM / 32)                           // 32

__global__ void __launch_bounds__(256)
gemm_bf16x3(const uint32_t* __restrict__ Ahi, const uint32_t* __restrict__ Alo,
            const uint32_t* __restrict__ Bthi, const uint32_t* __restrict__ Btlo,
            const float* __restrict__ bias, float* __restrict__ C, int N)
{
    extern __shared__ uint32_t gsm[];

    const int tid   = threadIdx.x;
    const int wid   = tid >> 5;
    const int lane  = tid & 31;
    const int g     = lane >> 2;
    const int q     = lane & 3;
    const int warpM = wid >> 2;            // 0..1
    const int warpN = wid & 3;             // 0..3
    const int m0    = blockIdx.y * 128;
    const int n0    = blockIdx.x * 128;

    const uint32_t smBase = smem_u32(gsm);

    const char* pl[4] = { (const char*)Ahi, (const char*)Alo,
                          (const char*)Bthi, (const char*)Btlo };

    auto load_tiles = [&](int it, int s) {
        const uint32_t st = smBase + s * GSTAGE_BYTES;
        const int kb = it * 64;                       // byte offset into row (32 bf16 = 64B)
#pragma unroll
        for (int j = 0; j < 8; j++) {
            int idx  = j * 256 + tid;                 // 0..2047
            int arr2 = idx >> 9;                      // 0 Ahi, 1 Alo, 2 Bhi, 3 Blo
            int rem  = idx & 511;
            int row  = rem >> 2;                      // 0..127
            int ch   = rem & 3;                       // 16B chunk within 64B
            uint32_t sa = st + (((arr2 >> 1) << 7) + row) * GROWB
                          + ((arr2 & 1) ? 64 : 0) + ch * 16;
            int row0 = (arr2 >> 1) ? n0 : m0;
            cpa16(sa, pl[arr2] + (size_t)(row0 + row) * (KW * 4) + kb + ch * 16);
        }
        CP_COMMIT();
    };

    float acc[4][4][4];
#pragma unroll
    for (int i = 0; i < 4; i++)
#pragma unroll
        for (int j = 0; j < 4; j++)
#pragma unroll
            for (int v = 0; v < 4; v++) acc[i][j][v] = 0.f;

    load_tiles(0, 0);

    // per-lane ldmatrix address components (proven in attention kernel)
    const uint32_t alane = ((lane & 7) + ((lane >> 3) & 1) * 8) * GROWB
                           + (lane >> 4) * 16;
    const uint32_t blane = ((lane & 7) + ((lane >> 4) << 3)) * GROWB
                           + ((lane >> 3) & 1) * 16;

    for (int it = 0; it < GNIT; it++) {
        const int s = it & 1;
        if (it + 1 < GNIT) { load_tiles(it + 1, s ^ 1); CP_WAIT(1); }
        else               { CP_WAIT(0); }
        __syncthreads();

        const uint32_t aB = smBase + s * GSTAGE_BYTES + (warpM * 64) * GROWB + alane;
        const uint32_t bB = smBase + s * GSTAGE_BYTES + (128 + warpN * 32) * GROWB + blane;

#pragma unroll
        for (int j = 0; j < 2; j++) {                 // two k16 steps per BK=32
            uint32_t ah[4][4], al[4][4];
#pragma unroll
            for (int mt = 0; mt < 4; mt++) {
                uint32_t base = aB + mt * (16 * GROWB) + j * 32;
                ldsm_x4(ah[mt][0], ah[mt][1], ah[mt][2], ah[mt][3], base);
                ldsm_x4(al[mt][0], al[mt][1], al[mt][2], al[mt][3], base + 64);
            }
#pragma unroll
            for (int nt = 0; nt < 2; nt++) {          // two n16 groups -> 4 n8 tiles
                uint32_t base = bB + nt * (16 * GROWB) + j * 32;
                uint32_t bh0, bh1, bh2, bh3, bl0, bl1, bl2, bl3;
                ldsm_x4(bh0, bh1, bh2, bh3, base);
                ldsm_x4(bl0, bl1, bl2, bl3, base + 64);
#pragma unroll
                for (int mt = 0; mt < 4; mt++) {
                    float* a0 = acc[mt][2 * nt];
                    float* a1 = acc[mt][2 * nt + 1];
                    mma_bf16(a0, ah[mt][0], ah[mt][1], ah[mt][2], ah[mt][3], bh0, bh1);
                    mma_bf16(a0, ah[mt][0], ah[mt][1], ah[mt][2], ah[mt][3], bl0, bl1);
                    mma_bf16(a0, al[mt][0], al[mt][1], al[mt][2], al[mt][3], bh0, bh1);
                    mma_bf16(a1, ah[mt][0], ah[mt][1], ah[mt][2], ah[mt][3], bh2, bh3);
                    mma_bf16(a1, ah[mt][0], ah[mt][1], ah[mt][2], ah[mt][3], bl2, bl3);
                    mma_bf16(a1, al[mt][0], al[mt][1], al[mt][2], al[mt][3], bh2, bh3);
                }
            }
        }
        __syncthreads();
    }

#pragma unroll
    for (int mt = 0; mt < 4; mt++) {
        const int rm = m0 + warpM * 64 + mt * 16 + g;
#pragma unroll
        for (int nt = 0; nt < 4; nt++) {
            const int cn = n0 + warpN * 32 + nt * 8 + 2 * q;
            float2 o0, o1;
            o0.x = acc[mt][nt][0] + bias[cn];
            o0.y = acc[mt][nt][1] + bias[cn + 1];
            o1.x = acc[mt][nt][2] + bias[cn];
            o1.y = acc[mt][nt][3] + bias[cn + 1];
            *(float2*)(C + (size_t)rm * N + cn)       = o0;
            *(float2*)(C + (size_t)(rm + 8) * N + cn) = o1;
        }
    }
}

// ================= prep: split x into bf16 planes =================
__global__ void __launch_bounds__(256)
split_x_kernel(const float* __restrict__ x,
               uint32_t* __restrict__ xhi, uint32_t* __restrict__ xlo)
{
    int i = blockIdx.x * blockDim.x + threadIdx.x;
    if (i >= M_TOT * EMB / 4) return;
    float4 v = ((const float4*)x)[i];
    uint32_t h0, l0, h1, l1;
    split2(v.x, v.y, h0, l0);
    split2(v.z, v.w, h1, l1);
    int w = i * 2;
    xhi[w] = h0; xhi[w + 1] = h1;
    xlo[w] = l0; xlo[w + 1] = l1;
}

// ================= prep: transpose + split weights =================
// W[K,N] -> Wt planes [N][K/2 words]. block (32,8), grid (N/32, K/32)
__global__ void __launch_bounds__(256)
transpose_split_w_kernel(const float* __restrict__ W,
                         uint32_t* __restrict__ wthi, uint32_t* __restrict__ wtlo,
                         int N)
{
    __shared__ float tile[32][33];
    const int k0 = blockIdx.y * 32, n0 = blockIdx.x * 32;
    const int tx = threadIdx.x, ty = threadIdx.y;
#pragma unroll
    for (int i = ty; i < 32; i += 8)
        tile[i][tx] = W[(size_t)(k0 + i) * N + n0 + tx];
    __syncthreads();
    if (tx < 16) {
#pragma unroll
        for (int i = ty; i < 32; i += 8) {
            uint32_t whi, wlo;
            split2(tile[2 * tx][i], tile[2 * tx + 1][i], whi, wlo);
            size_t w = (size_t)(n0 + i) * KW + k0 / 2 + tx;
            wthi[w] = whi;
            wtlo[w] = wlo;
        }
    }
}

// ================= prepass: split Q (scaled by 0.125*log2e) and K =================
#define QSCALE 0.180336879091324521f   // 0.125 * log2(e)

__global__ void __launch_bounds__(256)
split_qk_kernel(const float* __restrict__ qkv,
                uint32_t* __restrict__ qhi, uint32_t* __restrict__ qlo,
                uint32_t* __restrict__ khi, uint32_t* __restrict__ klo)
{
    int i = blockIdx.x * blockDim.x + threadIdx.x;
    if (i >= M_TOT * EMB / 4) return;
    int bt = i >> 8;
    int c4 = i & 255;
    const float* p = qkv + (size_t)bt * C3 + c4 * 4;
    float4 qv = *(const float4*)p;
    float4 kv = *(const float4*)(p + EMB);
    uint32_t h0, l0, h1, l1;
    int w = bt * (EMB / 2) + c4 * 2;
    split2(qv.x * QSCALE, qv.y * QSCALE, h0, l0);
    split2(qv.z * QSCALE, qv.w * QSCALE, h1, l1);
    qhi[w] = h0; qhi[w + 1] = h1; qlo[w] = l0; qlo[w + 1] = l1;
    split2(kv.x, kv.y, h0, l0);
    split2(kv.z, kv.w, h1, l1);
    khi[w] = h0; khi[w + 1] = h1; klo[w] = l0; klo[w + 1] = l1;
}

// ================= prepass: transpose+split V per head =================
__global__ void __launch_bounds__(256)
transpose_v_kernel(const float* __restrict__ qkv,
                   uint32_t* __restrict__ vthi, uint32_t* __restrict__ vtlo)
{
    __shared__ float tile[64][65];
    const int s0 = blockIdx.x * 64;
    const int h  = blockIdx.y;
    const int b  = blockIdx.z;
    const int tid = threadIdx.x;

#pragma unroll
    for (int j = 0; j < 16; j++) {
        int idx = tid + j * 256;
        int r = idx >> 6, d = idx & 63;
        tile[r][d] = qkv[(size_t)(b * SEQ + s0 + r) * C3 + 2 * EMB + h * HDIM + d];
    }
    __syncthreads();

    const int wv = tid & 31;
    const int dq = tid >> 5;
#pragma unroll
    for (int j = 0; j < 8; j++) {
        int d = dq * 8 + j;
        float e = tile[2 * wv][d];
        float o = tile[2 * wv + 1][d];
        uint32_t whi, wlo;
        split2(e, o, whi, wlo);
        size_t wi = ((size_t)(b * NHEAD + h) * HDIM + d) * (SEQ / 2) + s0 / 2 + wv;
        vthi[wi] = whi;
        vtlo[wi] = wlo;
    }
}

// ================= tensor-core causal flash attention =================
// 64-row Q tiles, 128 threads (4 warps), 2 CTAs/SM. bf16x3 + ldmatrix.
// Epilogue writes bf16 hi/lo planes (feeds proj GEMM directly).
#define ROWW 36
#define ROWB 144
#define Q_WORDS      (64 * ROWW)
#define ONES_WORDS   (16 * ROWW)
#define KV_ARR_WORDS (64 * ROWW)
#define KV_ARR_BYTES (KV_ARR_WORDS * 4)
#define STAGE_WORDS  (4 * KV_ARR_WORDS)
#define STAGE_BYTES  (STAGE_WORDS * 4)
#define ATT_SMEM_WORDS (2 * Q_WORDS + ONES_WORDS + 2 * STAGE_WORDS)
#define ATT_SMEM_BYTES (ATT_SMEM_WORDS * 4)       // 94464

__global__ void __launch_bounds__(128, 2)
attn_mma_kernel(const uint32_t* __restrict__ qhi, const uint32_t* __restrict__ qlo,
                const uint32_t* __restrict__ khi, const uint32_t* __restrict__ klo,
                const uint32_t* __restrict__ vthi, const uint32_t* __restrict__ vtlo,
                uint32_t* __restrict__ athi, uint32_t* __restrict__ atlo)
{
    extern __shared__ uint32_t sbuf[];
    uint32_t* Qhi  = sbuf;
    uint32_t* Qlo  = Qhi + Q_WORDS;
    uint32_t* Ones = Qlo + Q_WORDS;
    uint32_t* KV   = Ones + ONES_WORDS;

    const int qt   = (SEQ / 64 - 1) - blockIdx.x;
    const int h    = blockIdx.y;
    const int b    = blockIdx.z;
    const int tid  = threadIdx.x;
    const int w    = tid >> 5;
    const int lane = tid & 31;
    const int g    = lane >> 2;
    const int q    = lane & 3;

    const uint32_t kvS = smem_u32(KV);

    const char* qhiB = (const char*)qhi;
    const char* qloB = (const char*)qlo;
    const char* khiB = (const char*)khi;
    const char* kloB = (const char*)klo;
    const char* vhiB = (const char*)vthi;
    const char* vloB = (const char*)vtlo;
    const size_t qkRow0 = ((size_t)(b * SEQ) * EMB + h * HDIM) * 2;
    const size_t vRow0  = ((size_t)(b * NHEAD + h) * HDIM) * SEQ * 2;

    for (int i = tid; i < ONES_WORDS; i += 128)
        Ones[i] = (i < 8 * ROWW) ? 0x3F803F80u : 0u;

    {
        const uint32_t qs_hi = smem_u32(Qhi);
        const uint32_t qs_lo = smem_u32(Qlo);
#pragma unroll
        for (int j = 0; j < 8; j++) {
            int idx = j * 128 + tid;
            int plane = idx >> 9;
            int rem = idx & 511;
            int row = rem >> 3, ch = rem & 7;
            uint32_t sa = (plane ? qs_lo : qs_hi) + row * ROWB + ch * 16;
            const char* gp = (plane ? qloB : qhiB) +
                             qkRow0 + (size_t)(qt * 64 + row) * (EMB * 2) + ch * 16;
            cpa16(sa, gp);
        }
    }
    auto load_kv = [&](int kt, int s) {
        const uint32_t st = kvS + s * STAGE_BYTES;
#pragma unroll
        for (int j = 0; j < 16; j++) {
            int idx = j * 128 + tid;
            int arr = idx >> 9;
            int rem = idx & 511;
            int row = rem >> 3, ch = rem & 7;
            uint32_t sa = st + arr * KV_ARR_BYTES + row * ROWB + ch * 16;
            const char* gp;
            if (arr == 0)
                gp = khiB + qkRow0 + (size_t)(kt * 64 + row) * (EMB * 2) + ch * 16;
            else if (arr == 1)
                gp = kloB + qkRow0 + (size_t)(kt * 64 + row) * (EMB * 2) + ch * 16;
            else if (arr == 2)
                gp = vhiB + vRow0 + (size_t)row * (SEQ * 2) + kt * 128 + ch * 16;
            else
                gp = vloB + vRow0 + (size_t)row * (SEQ * 2) + kt * 128 + ch * 16;
            cpa16(sa, gp);
        }
    };
    load_kv(0, 0);
    CP_COMMIT();
    __syncthreads();

    const uint32_t kvlane = ((lane & 7) + ((lane >> 4) << 3)) * ROWB
                            + ((lane >> 3) & 1) * 16;
    uint32_t on0, on1, on2, on3;
    ldsm_x4(on0, on1, on2, on3, smem_u32(Ones) + kvlane);
    (void)on2; (void)on3;

    float o[8][4], ol[4];
#pragma unroll
    for (int t = 0; t < 8; t++)
#pragma unroll
        for (int v = 0; v < 4; v++) o[t][v] = 0.f;
#pragma unroll
    for (int v = 0; v < 4; v++) ol[v] = 0.f;
    float m0 = -1e30f, m1 = -1e30f;

    const int rb   = w * 16;
    const int row0 = qt * 64 + rb + g;
    const int row1 = row0 + 8;
    const int kend = qt + 1;

    const uint32_t qlane = (rb + (lane & 7) + ((lane >> 3) & 1) * 8) * ROWB
                           + (lane >> 4) * 16;
    const uint32_t qhiA = smem_u32(Qhi) + qlane;
    const uint32_t qloA = smem_u32(Qlo) + qlane;

    for (int kt = 0; kt < kend; kt++) {
        const int s = kt & 1;
        CP_WAIT(0);
        __syncthreads();
        if (kt + 1 < kend) { load_kv(kt + 1, s ^ 1); CP_COMMIT(); }

        const uint32_t stB  = kvS + s * STAGE_BYTES;
        const uint32_t khiA = stB + kvlane;
        const uint32_t kloA = khiA + KV_ARR_BYTES;
        const uint32_t vhiA = kloA + KV_ARR_BYTES;
        const uint32_t vloA = vhiA + KV_ARR_BYTES;

        float sc[8][4];
#pragma unroll
        for (int t = 0; t < 8; t++)
#pragma unroll
            for (int v = 0; v < 4; v++) sc[t][v] = 0.f;

#pragma unroll
        for (int j = 0; j < 4; j++) {
            uint32_t qh0, qh1, qh2, qh3, ql0, ql1, ql2, ql3;
            ldsm_x4(qh0, qh1, qh2, qh3, qhiA + j * 32);
            ldsm_x4(ql0, ql1, ql2, ql3, qloA + j * 32);
#pragma unroll
            for (int tp = 0; tp < 4; tp++) {
                uint32_t k0, k1, k2, k3, e0, e1, e2, e3;
                ldsm_x4(k0, k1, k2, k3, khiA + tp * (16 * ROWB) + j * 32);
                ldsm_x4(e0, e1, e2, e3, kloA + tp * (16 * ROWB) + j * 32);
                mma_bf16(sc[2 * tp],     qh0, qh1, qh2, qh3, k0, k1);
                mma_bf16(sc[2 * tp],     qh0, qh1, qh2, qh3, e0, e1);
                mma_bf16(sc[2 * tp],     ql0, ql1, ql2, ql3, k0, k1);
                mma_bf16(sc[2 * tp + 1], qh0, qh1, qh2, qh3, k2, k3);
                mma_bf16(sc[2 * tp + 1], qh0, qh1, qh2, qh3, e2, e3);
                mma_bf16(sc[2 * tp + 1], ql0, ql1, ql2, ql3, k2, k3);
            }
        }

        if (kt == qt) {
#pragma unroll
            for (int t = 0; t < 8; t++) {
                int col = kt * 64 + 8 * t + 2 * q;
                if (col     > row0) sc[t][0] = -1e30f;
                if (col + 1 > row0) sc[t][1] = -1e30f;
                if (col     > row1) sc[t][2] = -1e30f;
                if (col + 1 > row1) sc[t][3] = -1e30f;
            }
        }

        float mx0 = -1e30f, mx1 = -1e30f;
#pragma unroll
        for (int t = 0; t < 8; t++) {
            mx0 = fmaxf(mx0, fmaxf(sc[t][0], sc[t][1]));
            mx1 = fmaxf(mx1, fmaxf(sc[t][2], sc[t][3]));
        }
        mx0 = fmaxf(mx0, __shfl_xor_sync(0xffffffffu, mx0, 1));
        mx0 = fmaxf(mx0, __shfl_xor_sync(0xffffffffu, mx0, 2));
        mx1 = fmaxf(mx1, __shfl_xor_sync(0xffffffffu, mx1, 1));
        mx1 = fmaxf(mx1, __shfl_xor_sync(0xffffffffu, mx1, 2));

        float mn0 = fmaxf(m0, mx0), mn1 = fmaxf(m1, mx1);
        float a0 = exp2f(m0 - mn0), a1 = exp2f(m1 - mn1);
        m0 = mn0; m1 = mn1;
#pragma unroll
        for (int t = 0; t < 8; t++) {
            sc[t][0] = exp2f(sc[t][0] - mn0);
            sc[t][1] = exp2f(sc[t][1] - mn0);
            sc[t][2] = exp2f(sc[t][2] - mn1);
            sc[t][3] = exp2f(sc[t][3] - mn1);
        }
#pragma unroll
        for (int t = 0; t < 8; t++) {
            o[t][0] *= a0; o[t][1] *= a0;
            o[t][2] *= a1; o[t][3] *= a1;
        }
        ol[0] *= a0; ol[1] *= a0; ol[2] *= a1; ol[3] *= a1;

#pragma unroll
        for (int j = 0; j < 4; j++) {
            uint32_t ph0 = pack_bf16x2(sc[2*j][0],   sc[2*j][1]);
            uint32_t ph1 = pack_bf16x2(sc[2*j][2],   sc[2*j][3]);
            uint32_t ph2 = pack_bf16x2(sc[2*j+1][0], sc[2*j+1][1]);
            uint32_t ph3 = pack_bf16x2(sc[2*j+1][2], sc[2*j+1][3]);
            uint32_t pl0 = pack_bf16x2(sc[2*j][0]   - __uint_as_float(ph0 << 16),
                                       sc[2*j][1]   - __uint_as_float(ph0 & 0xFFFF0000u));
            uint32_t pl1 = pack_bf16x2(sc[2*j][2]   - __uint_as_float(ph1 << 16),
                                       sc[2*j][3]   - __uint_as_float(ph1 & 0xFFFF0000u));
            uint32_t pl2 = pack_bf16x2(sc[2*j+1][0] - __uint_as_float(ph2 << 16),
                                       sc[2*j+1][1] - __uint_as_float(ph2 & 0xFFFF0000u));
            uint32_t pl3 = pack_bf16x2(sc[2*j+1][2] - __uint_as_float(ph3 << 16),
                                       sc[2*j+1][3] - __uint_as_float(ph3 & 0xFFFF0000u));
            mma_bf16(ol, ph0, ph1, ph2, ph3, on0, on1);
            mma_bf16(ol, pl0, pl1, pl2, pl3, on0, on1);
#pragma unroll
            for (int tp = 0; tp < 4; tp++) {
                uint32_t v0, v1, v2, v3, u0, u1, u2, u3;
                ldsm_x4(v0, v1, v2, v3, vhiA + tp * (16 * ROWB) + j * 32);
                ldsm_x4(u0, u1, u2, u3, vloA + tp * (16 * ROWB) + j * 32);
                mma_bf16(o[2 * tp],     ph0, ph1, ph2, ph3, v0, v1);
                mma_bf16(o[2 * tp],     ph0, ph1, ph2, ph3, u0, u1);
                mma_bf16(o[2 * tp],     pl0, pl1, pl2, pl3, v0, v1);
                mma_bf16(o[2 * tp + 1], ph0, ph1, ph2, ph3, v2, v3);
                mma_bf16(o[2 * tp + 1], ph0, ph1, ph2, ph3, u2, u3);
                mma_bf16(o[2 * tp + 1], pl0, pl1, pl2, pl3, v2, v3);
            }
        }
        __syncthreads();
    }

    // epilogue: normalize and write bf16 hi/lo planes directly
    const float inv0 = 1.f / ol[0], inv1 = 1.f / ol[2];
    const size_t wrow0 = ((size_t)b * SEQ + row0) * (EMB / 2) + (h * HDIM) / 2;
#pragma unroll
    for (int t = 0; t < 8; t++) {
        const int c2 = 4 * t + q;
        uint32_t whi, wlo;
        split2(o[t][0] * inv0, o[t][1] * inv0, whi, wlo);
        athi[wrow0 + c2] = whi;
        atlo[wrow0 + c2] = wlo;
        split2(o[t][2] * inv1, o[t][3] * inv1, whi, wlo);
        athi[wrow0 + 8 * (EMB / 2) + c2] = whi;
        atlo[wrow0 + 8 * (EMB / 2) + c2] = wlo;
    }
}

// ---------------- launcher ----------------
extern "C" void kernel_launch(void* const* d_in, const int* in_sizes, int n_in,
                              void* d_out, int out_size)
{
    const float* x     = (const float*)d_in[0];
    const float* Wqkv  = (const float*)d_in[1];
    const float* bqkv  = (const float*)d_in[2];
    const float* Wproj = (const float*)d_in[3];
    const float* bproj = (const float*)d_in[4];
    float* out = (float*)d_out;

    float* qkv_p;
    uint32_t *xhi_p, *xlo_p, *wqthi_p, *wqtlo_p, *wpthi_p, *wptlo_p;
    uint32_t *athi_p, *atlo_p;
    uint32_t *qhi_p, *qlo_p, *khi_p, *klo_p, *vhi_p, *vlo_p;
    cudaGetSymbolAddress((void**)&qkv_p,   g_qkv);
    cudaGetSymbolAddress((void**)&xhi_p,   g_xhi);
    cudaGetSymbolAddress((void**)&xlo_p,   g_xlo);
    cudaGetSymbolAddress((void**)&wqthi_p, g_wqthi);
    cudaGetSymbolAddress((void**)&wqtlo_p, g_wqtlo);
    cudaGetSymbolAddress((void**)&wpthi_p, g_wpthi);
    cudaGetSymbolAddress((void**)&wptlo_p, g_wptlo);
    cudaGetSymbolAddress((void**)&athi_p,  g_athi);
    cudaGetSymbolAddress((void**)&atlo_p,  g_atlo);
    cudaGetSymbolAddress((void**)&qhi_p,   g_qhi);
    cudaGetSymbolAddress((void**)&qlo_p,   g_qlo);
    cudaGetSymbolAddress((void**)&khi_p,   g_khi);
    cudaGetSymbolAddress((void**)&klo_p,   g_klo);
    cudaGetSymbolAddress((void**)&vhi_p,   g_vthi);
    cudaGetSymbolAddress((void**)&vlo_p,   g_vtlo);

    cudaFuncSetAttribute(attn_mma_kernel, cudaFuncAttributeMaxDynamicSharedMemorySize,
                         (int)ATT_SMEM_BYTES);
    cudaFuncSetAttribute(gemm_bf16x3, cudaFuncAttributeMaxDynamicSharedMemorySize,
                         (int)GEMM_SMEM_BYTES);

    // 0) prep: split x; transpose+split weights
    split_x_kernel<<<(M_TOT * EMB / 4 + 255) / 256, 256>>>(x, xhi_p, xlo_p);
    transpose_split_w_kernel<<<dim3(C3 / 32, KDIM / 32), dim3(32, 8)>>>(Wqkv, wqthi_p, wqtlo_p, C3);
    transpose_split_w_kernel<<<dim3(EMB / 32, KDIM / 32), dim3(32, 8)>>>(Wproj, wpthi_p, wptlo_p, EMB);

    // 1) qkv = x @ W_qkv + b_qkv   (bf16x3 mma.sync)
    gemm_bf16x3<<<dim3(C3 / 128, M_TOT / 128), 256, GEMM_SMEM_BYTES>>>(
        xhi_p, xlo_p, wqthi_p, wqtlo_p, bqkv, qkv_p, C3);

    // 2a) pre-split Q/K, transpose+split V
    split_qk_kernel<<<(M_TOT * EMB / 4 + 255) / 256, 256>>>(qkv_p, qhi_p, qlo_p, khi_p, klo_p);
    transpose_v_kernel<<<dim3(SEQ / 64, NHEAD, BATCH), 256>>>(qkv_p, vhi_p, vlo_p);

    // 2b) causal attention -> bf16 planes
    attn_mma_kernel<<<dim3(SEQ / 64, NHEAD, BATCH), 128, ATT_SMEM_BYTES>>>(
        qhi_p, qlo_p, khi_p, klo_p, vhi_p, vlo_p, athi_p, atlo_p);

    // 3) out = att @ W_proj + b_proj  (bf16x3 mma.sync)
    gemm_bf16x3<<<dim3(EMB / 128, M_TOT / 128), 256, GEMM_SMEM_BYTES>>>(
        athi_p, atlo_p, wpthi_p, wptlo_p, bproj, out, EMB);
}

// round 14
// speedup vs baseline: 1.2955x; 1.2955x over previous
#include <cuda_runtime.h>
#include <cuda_bf16.h>
#include <math.h>
#include <stdint.h>

// ---------------- problem constants ----------------
#define BATCH  2
#define SEQ    2048
#define EMB    1024
#define NHEAD  16
#define HDIM   64
#define M_TOT  (BATCH * SEQ)       // 4096
#define C3     (3 * EMB)           // 3072
#define KDIM   1024

// ---------------- scratch ----------------
__device__ float    g_qkv[M_TOT * C3];        // fp32 V region (Q/K go straight to planes)
__device__ float    g_att[M_TOT * EMB];       // attention out (fp32)
__device__ uint32_t g_qhi[M_TOT * EMB / 2];   // Q*(0.125*log2e) planes
__device__ uint32_t g_qlo[M_TOT * EMB / 2];
__device__ uint32_t g_khi[M_TOT * EMB / 2];
__device__ uint32_t g_klo[M_TOT * EMB / 2];
__device__ uint32_t g_vthi[M_TOT * EMB / 2];  // V^T per head: [b][h][d][seq]
__device__ uint32_t g_vtlo[M_TOT * EMB / 2];

#define QSCALE 0.180336879091324521f   // 0.125 * log2(e)

// ================= helpers =================
__device__ __forceinline__ uint32_t smem_u32(const void* p) {
    uint32_t a;
    asm("{ .reg .u64 t; cvta.to.shared.u64 t, %1; cvt.u32.u64 %0, t; }" : "=r"(a) : "l"(p));
    return a;
}
__device__ __forceinline__ uint32_t tf32r_u(float x) {
    uint32_t r;
    asm("cvt.rna.tf32.f32 %0, %1;" : "=r"(r) : "f"(x));
    return r;
}
__device__ __forceinline__ void cpa16(uint32_t saddr, const void* g) {
    asm volatile("cp.async.cg.shared.global [%0], [%1], 16;" :: "r"(saddr), "l"(g));
}
#define CP_COMMIT()  asm volatile("cp.async.commit_group;")
#define CP_WAIT(n)   asm volatile("cp.async.wait_group %0;" :: "n"(n))

__device__ __forceinline__ void mma_tf32(float* d, const uint32_t* a, const uint32_t* b) {
    asm volatile(
        "mma.sync.aligned.m16n8k8.row.col.f32.tf32.tf32.f32 "
        "{%0,%1,%2,%3}, {%4,%5,%6,%7}, {%8,%9}, {%0,%1,%2,%3};"
        : "+f"(d[0]), "+f"(d[1]), "+f"(d[2]), "+f"(d[3])
        : "r"(a[0]), "r"(a[1]), "r"(a[2]), "r"(a[3]), "r"(b[0]), "r"(b[1]));
}
__device__ __forceinline__ void mma_bf16(float* d, uint32_t a0, uint32_t a1,
                                         uint32_t a2, uint32_t a3,
                                         uint32_t b0, uint32_t b1) {
    asm volatile(
        "mma.sync.aligned.m16n8k16.row.col.f32.bf16.bf16.f32 "
        "{%0,%1,%2,%3}, {%4,%5,%6,%7}, {%8,%9}, {%0,%1,%2,%3};"
        : "+f"(d[0]), "+f"(d[1]), "+f"(d[2]), "+f"(d[3])
        : "r"(a0), "r"(a1), "r"(a2), "r"(a3), "r"(b0), "r"(b1));
}
__device__ __forceinline__ void ldsm_x4(uint32_t& r0, uint32_t& r1, uint32_t& r2,
                                        uint32_t& r3, uint32_t addr) {
    asm volatile("ldmatrix.sync.aligned.m8n8.x4.shared.b16 {%0,%1,%2,%3}, [%4];"
                 : "=r"(r0), "=r"(r1), "=r"(r2), "=r"(r3) : "r"(addr));
}
__device__ __forceinline__ uint32_t pack_bf16x2(float e, float o) {
    uint32_t r;
    asm("cvt.rn.bf16x2.f32 %0, %1, %2;" : "=r"(r) : "f"(o), "f"(e));
    return r;
}
__device__ __forceinline__ void split2(float e, float o, uint32_t& whi, uint32_t& wlo) {
    whi = pack_bf16x2(e, o);
    float he = __uint_as_float(whi << 16);
    float ho = __uint_as_float(whi & 0xFFFF0000u);
    wlo = pack_bf16x2(e - he, o - ho);
}

// ================= tf32 mma.sync GEMM (453-proven core, fused epilogue) =================
// C = round(A) @ round(B) + bias.  CTA 128x256, BK=16, 8 warps (2Mx4N), warp 64x64.
// mode 0: plain fp32 C.  mode 1: QKV — Q/K regions write bf16 hi/lo planes, V fp32.
#define BM 128
#define BN 256
#define BK 16
#define NIT (KDIM / BK)
#define A_PAD 20
#define B_PAD 264
#define A_STAGE (BM * A_PAD)
#define B_STAGE (BK * B_PAD)
#define STG_WORDS (A_STAGE + B_STAGE)
#define GEMM_SMEM_BYTES (2 * STG_WORDS * 4)

__global__ void __launch_bounds__(256, 1)
gemm_tf32_mma(const float* __restrict__ A, const float* __restrict__ B,
              const float* __restrict__ bias, float* __restrict__ C, int N, int mode)
{
    extern __shared__ float gsm[];

    const int tid   = threadIdx.x;
    const int wid   = tid >> 5;
    const int lane  = tid & 31;
    const int g     = lane >> 2;
    const int q     = lane & 3;
    const int warpM = wid >> 2;
    const int warpN = wid & 3;
    const int m0    = blockIdx.y * BM;
    const int n0    = blockIdx.x * BN;

    const uint32_t smBase = smem_u32(gsm);

    auto load_tiles = [&](int it, int s) {
        const int k0 = it * BK;
        const uint32_t aBase = smBase + s * (STG_WORDS * 4);
        const uint32_t bBase = aBase + A_STAGE * 4;
#pragma unroll
        for (int j = 0; j < 2; j++) {
            int c = tid + j * 256;
            int r = c >> 2, seg = c & 3;
            cpa16(aBase + (r * A_PAD + seg * 4) * 4,
                  A + (size_t)(m0 + r) * KDIM + k0 + seg * 4);
        }
#pragma unroll
        for (int j = 0; j < 4; j++) {
            int c = tid + j * 256;
            int r = c >> 6, seg = c & 63;
            cpa16(bBase + (r * B_PAD + seg * 4) * 4,
                  B + (size_t)(k0 + r) * N + n0 + seg * 4);
        }
        CP_COMMIT();
    };

    float acc[4][8][4];
#pragma unroll
    for (int i = 0; i < 4; i++)
#pragma unroll
        for (int j = 0; j < 8; j++)
#pragma unroll
            for (int v = 0; v < 4; v++) acc[i][j][v] = 0.f;

    load_tiles(0, 0);

    const int mbase = warpM * 64;
    const int nbase = warpN * 64;

    for (int it = 0; it < NIT; it++) {
        const int s = it & 1;
        if (it + 1 < NIT) { load_tiles(it + 1, s ^ 1); CP_WAIT(1); }
        else              { CP_WAIT(0); }
        __syncthreads();

        const float* As = gsm + s * STG_WORDS;
        const float* Bs = As + A_STAGE;

#pragma unroll
        for (int kk = 0; kk < 2; kk++) {
            const int k = kk * 8;
            uint32_t af[4][4], bf[8][2];
#pragma unroll
            for (int mt = 0; mt < 4; mt++) {
                const int rb = mbase + mt * 16;
                af[mt][0] = tf32r_u(As[(rb + g)     * A_PAD + k + q]);
                af[mt][1] = tf32r_u(As[(rb + g + 8) * A_PAD + k + q]);
                af[mt][2] = tf32r_u(As[(rb + g)     * A_PAD + k + q + 4]);
                af[mt][3] = tf32r_u(As[(rb + g + 8) * A_PAD + k + q + 4]);
            }
#pragma unroll
            for (int nt = 0; nt < 8; nt++) {
                const int cb = nbase + nt * 8;
                bf[nt][0] = tf32r_u(Bs[(k + q)     * B_PAD + cb + g]);
                bf[nt][1] = tf32r_u(Bs[(k + q + 4) * B_PAD + cb + g]);
            }
#pragma unroll
            for (int mt = 0; mt < 4; mt++)
#pragma unroll
                for (int nt = 0; nt < 8; nt++)
                    mma_tf32(acc[mt][nt], af[mt], bf[nt]);
        }
        __syncthreads();
    }

    // -------- epilogue --------
    if (mode == 0) {
#pragma unroll
        for (int mt = 0; mt < 4; mt++) {
            const int rm = m0 + mbase + mt * 16 + g;
#pragma unroll
            for (int nt = 0; nt < 8; nt++) {
                const int cn = n0 + nbase + nt * 8 + 2 * q;
                float2 o0, o1;
                o0.x = acc[mt][nt][0] + bias[cn];
                o0.y = acc[mt][nt][1] + bias[cn + 1];
                o1.x = acc[mt][nt][2] + bias[cn];
                o1.y = acc[mt][nt][3] + bias[cn + 1];
                *(float2*)(C + (size_t)rm * N + cn)       = o0;
                *(float2*)(C + (size_t)(rm + 8) * N + cn) = o1;
            }
        }
    } else {
        const int region = n0 >> 10;                 // 0=Q, 1=K, 2=V (BN=256 divides 1024)
        const float sc = (region == 0) ? QSCALE : 1.0f;
        uint32_t* dsthi = (region == 0) ? g_qhi : g_khi;
        uint32_t* dstlo = (region == 0) ? g_qlo : g_klo;
#pragma unroll
        for (int mt = 0; mt < 4; mt++) {
            const int rm = m0 + mbase + mt * 16 + g;
#pragma unroll
            for (int nt = 0; nt < 8; nt++) {
                const int cn = n0 + nbase + nt * 8 + 2 * q;
                float e0 = acc[mt][nt][0] + bias[cn];
                float o0 = acc[mt][nt][1] + bias[cn + 1];
                float e1 = acc[mt][nt][2] + bias[cn];
                float o1 = acc[mt][nt][3] + bias[cn + 1];
                if (region == 2) {
                    *(float2*)(C + (size_t)rm * C3 + cn)       = make_float2(e0, o0);
                    *(float2*)(C + (size_t)(rm + 8) * C3 + cn) = make_float2(e1, o1);
                } else {
                    const int cw = (cn & 1023) >> 1;
                    uint32_t whi, wlo;
                    split2(e0 * sc, o0 * sc, whi, wlo);
                    dsthi[(size_t)rm * (EMB / 2) + cw] = whi;
                    dstlo[(size_t)rm * (EMB / 2) + cw] = wlo;
                    split2(e1 * sc, o1 * sc, whi, wlo);
                    dsthi[(size_t)(rm + 8) * (EMB / 2) + cw] = whi;
                    dstlo[(size_t)(rm + 8) * (EMB / 2) + cw] = wlo;
                }
            }
        }
    }
}

// ================= prepass: transpose+split V per head =================
__global__ void __launch_bounds__(256)
transpose_v_kernel(const float* __restrict__ qkv,
                   uint32_t* __restrict__ vthi, uint32_t* __restrict__ vtlo)
{
    __shared__ float tile[64][65];
    const int s0 = blockIdx.x * 64;
    const int h  = blockIdx.y;
    const int b  = blockIdx.z;
    const int tid = threadIdx.x;

#pragma unroll
    for (int j = 0; j < 16; j++) {
        int idx = tid + j * 256;
        int r = idx >> 6, d = idx & 63;
        tile[r][d] = qkv[(size_t)(b * SEQ + s0 + r) * C3 + 2 * EMB + h * HDIM + d];
    }
    __syncthreads();

    const int wv = tid & 31;
    const int dq = tid >> 5;
#pragma unroll
    for (int j = 0; j < 8; j++) {
        int d = dq * 8 + j;
        float e = tile[2 * wv][d];
        float o = tile[2 * wv + 1][d];
        uint32_t whi, wlo;
        split2(e, o, whi, wlo);
        size_t wi = ((size_t)(b * NHEAD + h) * HDIM + d) * (SEQ / 2) + s0 / 2 + wv;
        vthi[wi] = whi;
        vtlo[wi] = wlo;
    }
}

// ================= tensor-core causal flash attention (453-proven) =================
#define ROWW 36
#define ROWB 144
#define Q_WORDS      (64 * ROWW)
#define ONES_WORDS   (16 * ROWW)
#define KV_ARR_WORDS (64 * ROWW)
#define KV_ARR_BYTES (KV_ARR_WORDS * 4)
#define STAGE_WORDS  (4 * KV_ARR_WORDS)
#define STAGE_BYTES  (STAGE_WORDS * 4)
#define ATT_SMEM_WORDS (2 * Q_WORDS + ONES_WORDS + 2 * STAGE_WORDS)
#define ATT_SMEM_BYTES (ATT_SMEM_WORDS * 4)       // 94464

__global__ void __launch_bounds__(128, 2)
attn_mma_kernel(const uint32_t* __restrict__ qhi, const uint32_t* __restrict__ qlo,
                const uint32_t* __restrict__ khi, const uint32_t* __restrict__ klo,
                const uint32_t* __restrict__ vthi, const uint32_t* __restrict__ vtlo,
                float* __restrict__ out)
{
    extern __shared__ uint32_t sbuf[];
    uint32_t* Qhi  = sbuf;
    uint32_t* Qlo  = Qhi + Q_WORDS;
    uint32_t* Ones = Qlo + Q_WORDS;
    uint32_t* KV   = Ones + ONES_WORDS;

    const int qt   = (SEQ / 64 - 1) - blockIdx.x;
    const int h    = blockIdx.y;
    const int b    = blockIdx.z;
    const int tid  = threadIdx.x;
    const int w    = tid >> 5;
    const int lane = tid & 31;
    const int g    = lane >> 2;
    const int q    = lane & 3;

    const uint32_t kvS = smem_u32(KV);

    const char* qhiB = (const char*)qhi;
    const char* qloB = (const char*)qlo;
    const char* khiB = (const char*)khi;
    const char* kloB = (const char*)klo;
    const char* vhiB = (const char*)vthi;
    const char* vloB = (const char*)vtlo;
    const size_t qkRow0 = ((size_t)(b * SEQ) * EMB + h * HDIM) * 2;
    const size_t vRow0  = ((size_t)(b * NHEAD + h) * HDIM) * SEQ * 2;

    for (int i = tid; i < ONES_WORDS; i += 128)
        Ones[i] = (i < 8 * ROWW) ? 0x3F803F80u : 0u;

    {
        const uint32_t qs_hi = smem_u32(Qhi);
        const uint32_t qs_lo = smem_u32(Qlo);
#pragma unroll
        for (int j = 0; j < 8; j++) {
            int idx = j * 128 + tid;
            int plane = idx >> 9;
            int rem = idx & 511;
            int row = rem >> 3, ch = rem & 7;
            uint32_t sa = (plane ? qs_lo : qs_hi) + row * ROWB + ch * 16;
            const char* gp = (plane ? qloB : qhiB) +
                             qkRow0 + (size_t)(qt * 64 + row) * (EMB * 2) + ch * 16;
            cpa16(sa, gp);
        }
    }
    auto load_kv = [&](int kt, int s) {
        const uint32_t st = kvS + s * STAGE_BYTES;
#pragma unroll
        for (int j = 0; j < 16; j++) {
            int idx = j * 128 + tid;
            int arr = idx >> 9;
            int rem = idx & 511;
            int row = rem >> 3, ch = rem & 7;
            uint32_t sa = st + arr * KV_ARR_BYTES + row * ROWB + ch * 16;
            const char* gp;
            if (arr == 0)
                gp = khiB + qkRow0 + (size_t)(kt * 64 + row) * (EMB * 2) + ch * 16;
            else if (arr == 1)
                gp = kloB + qkRow0 + (size_t)(kt * 64 + row) * (EMB * 2) + ch * 16;
            else if (arr == 2)
                gp = vhiB + vRow0 + (size_t)row * (SEQ * 2) + kt * 128 + ch * 16;
            else
                gp = vloB + vRow0 + (size_t)row * (SEQ * 2) + kt * 128 + ch * 16;
            cpa16(sa, gp);
        }
    };
    load_kv(0, 0);
    CP_COMMIT();
    __syncthreads();

    const uint32_t kvlane = ((lane & 7) + ((lane >> 4) << 3)) * ROWB
                            + ((lane >> 3) & 1) * 16;
    uint32_t on0, on1, on2, on3;
    ldsm_x4(on0, on1, on2, on3, smem_u32(Ones) + kvlane);
    (void)on2; (void)on3;

    float o[8][4], ol[4];
#pragma unroll
    for (int t = 0; t < 8; t++)
#pragma unroll
        for (int v = 0; v < 4; v++) o[t][v] = 0.f;
#pragma unroll
    for (int v = 0; v < 4; v++) ol[v] = 0.f;
    float m0 = -1e30f, m1 = -1e30f;

    const int rb   = w * 16;
    const int row0 = qt * 64 + rb + g;
    const int row1 = row0 + 8;
    const int kend = qt + 1;

    const uint32_t qlane = (rb + (lane & 7) + ((lane >> 3) & 1) * 8) * ROWB
                           + (lane >> 4) * 16;
    const uint32_t qhiA = smem_u32(Qhi) + qlane;
    const uint32_t qloA = smem_u32(Qlo) + qlane;

    for (int kt = 0; kt < kend; kt++) {
        const int s = kt & 1;
        CP_WAIT(0);
        __syncthreads();
        if (kt + 1 < kend) { load_kv(kt + 1, s ^ 1); CP_COMMIT(); }

        const uint32_t stB  = kvS + s * STAGE_BYTES;
        const uint32_t khiA = stB + kvlane;
        const uint32_t kloA = khiA + KV_ARR_BYTES;
        const uint32_t vhiA = kloA + KV_ARR_BYTES;
        const uint32_t vloA = vhiA + KV_ARR_BYTES;

        float scr[8][4];
#pragma unroll
        for (int t = 0; t < 8; t++)
#pragma unroll
            for (int v = 0; v < 4; v++) scr[t][v] = 0.f;

#pragma unroll
        for (int j = 0; j < 4; j++) {
            uint32_t qh0, qh1, qh2, qh3, ql0, ql1, ql2, ql3;
            ldsm_x4(qh0, qh1, qh2, qh3, qhiA + j * 32);
            ldsm_x4(ql0, ql1, ql2, ql3, qloA + j * 32);
#pragma unroll
            for (int tp = 0; tp < 4; tp++) {
                uint32_t k0, k1, k2, k3, e0, e1, e2, e3;
                ldsm_x4(k0, k1, k2, k3, khiA + tp * (16 * ROWB) + j * 32);
                ldsm_x4(e0, e1, e2, e3, kloA + tp * (16 * ROWB) + j * 32);
                mma_bf16(scr[2 * tp],     qh0, qh1, qh2, qh3, k0, k1);
                mma_bf16(scr[2 * tp],     qh0, qh1, qh2, qh3, e0, e1);
                mma_bf16(scr[2 * tp],     ql0, ql1, ql2, ql3, k0, k1);
                mma_bf16(scr[2 * tp + 1], qh0, qh1, qh2, qh3, k2, k3);
                mma_bf16(scr[2 * tp + 1], qh0, qh1, qh2, qh3, e2, e3);
                mma_bf16(scr[2 * tp + 1], ql0, ql1, ql2, ql3, k2, k3);
            }
        }

        if (kt == qt) {
#pragma unroll
            for (int t = 0; t < 8; t++) {
                int col = kt * 64 + 8 * t + 2 * q;
                if (col     > row0) scr[t][0] = -1e30f;
                if (col + 1 > row0) scr[t][1] = -1e30f;
                if (col     > row1) scr[t][2] = -1e30f;
                if (col + 1 > row1) scr[t][3] = -1e30f;
            }
        }

        float mx0 = -1e30f, mx1 = -1e30f;
#pragma unroll
        for (int t = 0; t < 8; t++) {
            mx0 = fmaxf(mx0, fmaxf(scr[t][0], scr[t][1]));
            mx1 = fmaxf(mx1, fmaxf(scr[t][2], scr[t][3]));
        }
        mx0 = fmaxf(mx0, __shfl_xor_sync(0xffffffffu, mx0, 1));
        mx0 = fmaxf(mx0, __shfl_xor_sync(0xffffffffu, mx0, 2));
        mx1 = fmaxf(mx1, __shfl_xor_sync(0xffffffffu, mx1, 1));
        mx1 = fmaxf(mx1, __shfl_xor_sync(0xffffffffu, mx1, 2));

        float mn0 = fmaxf(m0, mx0), mn1 = fmaxf(m1, mx1);
        float a0 = exp2f(m0 - mn0), a1 = exp2f(m1 - mn1);
        m0 = mn0; m1 = mn1;
#pragma unroll
        for (int t = 0; t < 8; t++) {
            scr[t][0] = exp2f(scr[t][0] - mn0);
            scr[t][1] = exp2f(scr[t][1] - mn0);
            scr[t][2] = exp2f(scr[t][2] - mn1);
            scr[t][3] = exp2f(scr[t][3] - mn1);
        }
#pragma unroll
        for (int t = 0; t < 8; t++) {
            o[t][0] *= a0; o[t][1] *= a0;
            o[t][2] *= a1; o[t][3] *= a1;
        }
        ol[0] *= a0; ol[1] *= a0; ol[2] *= a1; ol[3] *= a1;

#pragma unroll
        for (int j = 0; j < 4; j++) {
            uint32_t ph0 = pack_bf16x2(scr[2*j][0],   scr[2*j][1]);
            uint32_t ph1 = pack_bf16x2(scr[2*j][2],   scr[2*j][3]);
            uint32_t ph2 = pack_bf16x2(scr[2*j+1][0], scr[2*j+1][1]);
            uint32_t ph3 = pack_bf16x2(scr[2*j+1][2], scr[2*j+1][3]);
            uint32_t pl0 = pack_bf16x2(scr[2*j][0]   - __uint_as_float(ph0 << 16),
                                       scr[2*j][1]   - __uint_as_float(ph0 & 0xFFFF0000u));
            uint32_t pl1 = pack_bf16x2(scr[2*j][2]   - __uint_as_float(ph1 << 16),
                                       scr[2*j][3]   - __uint_as_float(ph1 & 0xFFFF0000u));
            uint32_t pl2 = pack_bf16x2(scr[2*j+1][0] - __uint_as_float(ph2 << 16),
                                       scr[2*j+1][1] - __uint_as_float(ph2 & 0xFFFF0000u));
            uint32_t pl3 = pack_bf16x2(scr[2*j+1][2] - __uint_as_float(ph3 << 16),
                                       scr[2*j+1][3] - __uint_as_float(ph3 & 0xFFFF0000u));
            mma_bf16(ol, ph0, ph1, ph2, ph3, on0, on1);
            mma_bf16(ol, pl0, pl1, pl2, pl3, on0, on1);
#pragma unroll
            for (int tp = 0; tp < 4; tp++) {
                uint32_t v0, v1, v2, v3, u0, u1, u2, u3;
                ldsm_x4(v0, v1, v2, v3, vhiA + tp * (16 * ROWB) + j * 32);
                ldsm_x4(u0, u1, u2, u3, vloA + tp * (16 * ROWB) + j * 32);
                mma_bf16(o[2 * tp],     ph0, ph1, ph2, ph3, v0, v1);
                mma_bf16(o[2 * tp],     ph0, ph1, ph2, ph3, u0, u1);
                mma_bf16(o[2 * tp],     pl0, pl1, pl2, pl3, v0, v1);
                mma_bf16(o[2 * tp + 1], ph0, ph1, ph2, ph3, v2, v3);
                mma_bf16(o[2 * tp + 1], ph0, ph1, ph2, ph3, u2, u3);
                mma_bf16(o[2 * tp + 1], pl0, pl1, pl2, pl3, v2, v3);
            }
        }
        __syncthreads();
    }

    const float inv0 = 1.f / ol[0], inv1 = 1.f / ol[2];
    const size_t ob0 = ((size_t)b * SEQ + row0) * EMB + h * HDIM;
#pragma unroll
    for (int t = 0; t < 8; t++) {
        const int col = 8 * t + 2 * q;
        float2 w0, w1;
        w0.x = o[t][0] * inv0; w0.y = o[t][1] * inv0;
        w1.x = o[t][2] * inv1; w1.y = o[t][3] * inv1;
        *(float2*)(out + ob0 + col)            = w0;
        *(float2*)(out + ob0 + 8 * EMB + col)  = w1;
    }
}

// ---------------- launcher ----------------
extern "C" void kernel_launch(void* const* d_in, const int* in_sizes, int n_in,
                              void* d_out, int out_size)
{
    const float* x     = (const float*)d_in[0];
    const float* Wqkv  = (const float*)d_in[1];
    const float* bqkv  = (const float*)d_in[2];
    const float* Wproj = (const float*)d_in[3];
    const float* bproj = (const float*)d_in[4];
    float* out = (float*)d_out;

    float *qkv_p, *att_p;
    uint32_t *qhi_p, *qlo_p, *khi_p, *klo_p, *vhi_p, *vlo_p;
    cudaGetSymbolAddress((void**)&qkv_p, g_qkv);
    cudaGetSymbolAddress((void**)&att_p, g_att);
    cudaGetSymbolAddress((void**)&qhi_p, g_qhi);
    cudaGetSymbolAddress((void**)&qlo_p, g_qlo);
    cudaGetSymbolAddress((void**)&khi_p, g_khi);
    cudaGetSymbolAddress((void**)&klo_p, g_klo);
    cudaGetSymbolAddress((void**)&vhi_p, g_vthi);
    cudaGetSymbolAddress((void**)&vlo_p, g_vtlo);

    cudaFuncSetAttribute(attn_mma_kernel, cudaFuncAttributeMaxDynamicSharedMemorySize,
                         (int)ATT_SMEM_BYTES);
    cudaFuncSetAttribute(gemm_tf32_mma, cudaFuncAttributeMaxDynamicSharedMemorySize,
                         (int)GEMM_SMEM_BYTES);

    // 1) qkv GEMM with fused Q/K split epilogue (V written fp32 into g_qkv)
    gemm_tf32_mma<<<dim3(C3 / BN, M_TOT / BM), 256, GEMM_SMEM_BYTES>>>(
        x, Wqkv, bqkv, qkv_p, C3, 1);

    // 2a) transpose+split V
    transpose_v_kernel<<<dim3(SEQ / 64, NHEAD, BATCH), 256>>>(qkv_p, vhi_p, vlo_p);

    // 2b) causal attention (bf16x3)
    attn_mma_kernel<<<dim3(SEQ / 64, NHEAD, BATCH), 128, ATT_SMEM_BYTES>>>(
        qhi_p, qlo_p, khi_p, klo_p, vhi_p, vlo_p, att_p);

    // 3) out = att @ W_proj + b_proj
    gemm_tf32_mma<<<dim3(EMB / BN, M_TOT / BM), 256, GEMM_SMEM_BYTES>>>(
        att_p, Wproj, bproj, out, EMB, 0);
}